// round 14
// baseline (speedup 1.0000x reference)
#include <cuda_runtime.h>
#include <cstdint>

#define B_  4
#define L_  2048
#define D_  512
#define DK_ 256
#define BL_ (B_ * L_)

// Scratch (allocation-free per harness rules)
__device__ float g_Q[BL_ * DK_];
__device__ float g_K[BL_ * DK_];
__device__ float g_Vt[(size_t)D_ * BL_];        // V transposed: [512, 8192]
__device__ float g_QE[(size_t)BL_ * L_];
__device__ float g_S[(size_t)BL_ * L_];

__device__ __forceinline__ uint32_t cvt_tf32(float x) {
    uint32_t r;
    asm("cvt.rna.tf32.f32 %0, %1;" : "=r"(r) : "f"(x));
    return r;
}

__device__ __forceinline__ void mma_tf32(float c[4], const uint32_t a[4], const uint32_t b[2]) {
    asm volatile(
        "mma.sync.aligned.m16n8k8.row.col.f32.tf32.tf32.f32 "
        "{%0,%1,%2,%3},{%4,%5,%6,%7},{%8,%9},{%0,%1,%2,%3};"
        : "+f"(c[0]), "+f"(c[1]), "+f"(c[2]), "+f"(c[3])
        : "r"(a[0]), "r"(a[1]), "r"(a[2]), "r"(a[3]), "r"(b[0]), "r"(b[1]));
}

__device__ __forceinline__ void ldsm4(uint32_t& r0, uint32_t& r1, uint32_t& r2, uint32_t& r3,
                                      uint32_t addr) {
    asm volatile("ldmatrix.sync.aligned.m8n8.x4.shared.b16 {%0,%1,%2,%3}, [%4];"
                 : "=r"(r0), "=r"(r1), "=r"(r2), "=r"(r3) : "r"(addr));
}

// ---------------------------------------------------------------------------
// TF32 tensor-core GEMM (R8-proven structure: static smem, single-stage,
// register prefetch, ldmatrix fragments). Block tile 128x128, K-chunk 32,
// 256 threads = 8 warps (2x4 warp grid, warp tile 64x32), fp32 accumulate.
//   TRANS_B=false: C = A[M,K] * B[K,N]   (B row stride ldB = N)
//   TRANS_B=true : C = A[M,K] * B[N,K]^T (B row stride ldB)
//   SKEW         : C = (A*B^T + skew(QE)) * 1/16
//   TRANS_OUT    : write C transposed: Ct[n][m], leading dim BL_ (V proj only)
// ---------------------------------------------------------------------------
template <bool TRANS_B, bool SKEW, bool TRANS_OUT>
__global__ __launch_bounds__(256)
void tgemm(const float* __restrict__ A, const float* __restrict__ Bm,
           float* __restrict__ C, int M, int N, int Kd, int ldB,
           long long sA, long long sB, long long sC,
           const float* __restrict__ QE)
{
    __shared__ uint32_t As[128 * 36];
    __shared__ uint32_t Bs[TRANS_B ? (128 * 36) : (32 * 136)];

    const int bz = blockIdx.z;
    A  += (size_t)bz * sA;
    Bm += (size_t)bz * sB;
    C  += (size_t)bz * sC;

    const int bm = blockIdx.y * 128;
    const int bn = blockIdx.x * 128;
    const int tid  = threadIdx.x;
    const int lane = tid & 31;
    const int warp = tid >> 5;
    const int wm = warp & 1;   // 0..1  (64-row slab)
    const int wn = warp >> 1;  // 0..3  (32-col slab)

    const int arow  = tid >> 3;          // 0..31
    const int acol4 = (tid & 7) << 2;    // 0,4,..28
    const int brow  = tid >> 5;          // 0..7   (NN)
    const int bcol4 = (tid & 31) << 2;   // 0..124 (NN)

    // ldmatrix per-lane base addresses (bytes)
    const uint32_t asm0 = (uint32_t)__cvta_generic_to_shared(As);
    const uint32_t bsm0 = (uint32_t)__cvta_generic_to_shared(Bs);
    const int l7 = lane & 7;
    const int lA_m = (lane >> 3) & 1;
    const int lA_k = lane >> 4;
    uint32_t aaddr[4];
#pragma unroll
    for (int mi = 0; mi < 4; mi++)
        aaddr[mi] = asm0 + ((wm * 64 + mi * 16 + l7 + 8 * lA_m) * 36 + 4 * lA_k) * 4;
    uint32_t baddr[2];
    if (TRANS_B) {
        const int lB_n = lane >> 4;
        const int lB_k = (lane >> 3) & 1;
#pragma unroll
        for (int n2 = 0; n2 < 2; n2++)
            baddr[n2] = bsm0 + ((wn * 32 + n2 * 16 + l7 + 8 * lB_n) * 36 + 4 * lB_k) * 4;
    }

    float acc[4][4][4];
#pragma unroll
    for (int i = 0; i < 4; i++)
#pragma unroll
        for (int j = 0; j < 4; j++)
#pragma unroll
            for (int e = 0; e < 4; e++) acc[i][j][e] = 0.f;

    float4 ra[4], rb[4];

    // ---- prologue global load (k0 = 0) ----
#pragma unroll
    for (int i = 0; i < 4; i++)
        ra[i] = *reinterpret_cast<const float4*>(
            A + (size_t)(bm + arow + 32 * i) * Kd + acol4);
#pragma unroll
    for (int i = 0; i < 4; i++) {
        if (TRANS_B)
            rb[i] = *reinterpret_cast<const float4*>(
                Bm + (size_t)(bn + arow + 32 * i) * ldB + acol4);
        else
            rb[i] = *reinterpret_cast<const float4*>(
                Bm + (size_t)(brow + 8 * i) * ldB + bn + bcol4);
    }

    for (int k0 = 0; k0 < Kd; k0 += 32) {
        // ---- store tiles to smem (cvt to tf32 bits) ----
#pragma unroll
        for (int i = 0; i < 4; i++)
            *reinterpret_cast<uint4*>(&As[(arow + 32 * i) * 36 + acol4]) =
                make_uint4(cvt_tf32(ra[i].x), cvt_tf32(ra[i].y),
                           cvt_tf32(ra[i].z), cvt_tf32(ra[i].w));
#pragma unroll
        for (int i = 0; i < 4; i++) {
            if (TRANS_B)
                *reinterpret_cast<uint4*>(&Bs[(arow + 32 * i) * 36 + acol4]) =
                    make_uint4(cvt_tf32(rb[i].x), cvt_tf32(rb[i].y),
                               cvt_tf32(rb[i].z), cvt_tf32(rb[i].w));
            else
                *reinterpret_cast<uint4*>(&Bs[(brow + 8 * i) * 136 + bcol4]) =
                    make_uint4(cvt_tf32(rb[i].x), cvt_tf32(rb[i].y),
                               cvt_tf32(rb[i].z), cvt_tf32(rb[i].w));
        }
        __syncthreads();

        // ---- prefetch next chunk into registers ----
        if (k0 + 32 < Kd) {
            const int kn = k0 + 32;
#pragma unroll
            for (int i = 0; i < 4; i++)
                ra[i] = *reinterpret_cast<const float4*>(
                    A + (size_t)(bm + arow + 32 * i) * Kd + kn + acol4);
#pragma unroll
            for (int i = 0; i < 4; i++) {
                if (TRANS_B)
                    rb[i] = *reinterpret_cast<const float4*>(
                        Bm + (size_t)(bn + arow + 32 * i) * ldB + kn + acol4);
                else
                    rb[i] = *reinterpret_cast<const float4*>(
                        Bm + (size_t)(kn + brow + 8 * i) * ldB + bn + bcol4);
            }
        }

        // ---- compute: 4 k8-steps, fragments via ldmatrix ----
#pragma unroll
        for (int kb = 0; kb < 4; kb++) {
            const uint32_t koff = (uint32_t)(kb * 8 * 4);  // bytes
            uint32_t af[4][4];
#pragma unroll
            for (int mi = 0; mi < 4; mi++)
                ldsm4(af[mi][0], af[mi][1], af[mi][2], af[mi][3], aaddr[mi] + koff);
            uint32_t bf[4][2];
            if (TRANS_B) {
#pragma unroll
                for (int n2 = 0; n2 < 2; n2++)
                    ldsm4(bf[2 * n2][0], bf[2 * n2][1], bf[2 * n2 + 1][0], bf[2 * n2 + 1][1],
                          baddr[n2] + koff);
            } else {
                const int kk = kb * 8;
#pragma unroll
                for (int ni = 0; ni < 4; ni++) {
                    const int n = wn * 32 + ni * 8 + (lane >> 2);
                    bf[ni][0] = Bs[(kk + (lane & 3)) * 136 + n];
                    bf[ni][1] = Bs[(kk + 4 + (lane & 3)) * 136 + n];
                }
            }
#pragma unroll
            for (int mi = 0; mi < 4; mi++)
#pragma unroll
                for (int ni = 0; ni < 4; ni++)
                    mma_tf32(acc[mi][ni], af[mi], bf[ni]);
        }
        __syncthreads();
    }

    // ---- epilogue ----
    if (TRANS_OUT) {
        // write C transposed: Ct[n][m], leading dim BL_ (Vt production)
#pragma unroll
        for (int mi = 0; mi < 4; mi++) {
            const int r0 = bm + wm * 64 + mi * 16 + (lane >> 2);
#pragma unroll
            for (int ni = 0; ni < 4; ni++) {
                const int c0 = bn + wn * 32 + ni * 8 + 2 * (lane & 3);
#pragma unroll
                for (int e = 0; e < 4; e++) {
                    const int r = r0 + 8 * (e >> 1);
                    const int c = c0 + (e & 1);
                    C[(size_t)c * BL_ + r] = acc[mi][ni][e];
                }
            }
        }
    } else if (!SKEW) {
#pragma unroll
        for (int mi = 0; mi < 4; mi++) {
            const int r0 = bm + wm * 64 + mi * 16 + (lane >> 2);
#pragma unroll
            for (int ni = 0; ni < 4; ni++) {
                const int c0 = bn + wn * 32 + ni * 8 + 2 * (lane & 3);
                *reinterpret_cast<float2*>(C + (size_t)r0 * N + c0) =
                    make_float2(acc[mi][ni][0], acc[mi][ni][1]);
                *reinterpret_cast<float2*>(C + (size_t)(r0 + 8) * N + c0) =
                    make_float2(acc[mi][ni][2], acc[mi][ni][3]);
            }
        }
    } else {
        // Srel[l,m] = QE[l, m-l+L-1] (m<=l); 0 (m==l+1); QE[l+1, m-l-2] (m>=l+2)
        const float scale = 0.0625f;  // 1/sqrt(256)
        const int b = blockIdx.z;
#pragma unroll
        for (int mi = 0; mi < 4; mi++) {
            const int rbase = bm + wm * 64 + mi * 16 + (lane >> 2);
#pragma unroll
            for (int ni = 0; ni < 4; ni++) {
                const int c0 = bn + wn * 32 + ni * 8 + 2 * (lane & 3);
#pragma unroll
                for (int h = 0; h < 2; h++) {
                    const int l = rbase + 8 * h;
                    const size_t row0 = (size_t)(b * L_ + l) * L_;
                    const size_t row1 = (size_t)(b * L_ + l + 1) * L_;
                    float out[2];
#pragma unroll
                    for (int e = 0; e < 2; e++) {
                        const int m = c0 + e;
                        float srel;
                        if (m <= l)          srel = QE[row0 + (m - l + L_ - 1)];
                        else if (m == l + 1) srel = 0.f;
                        else                 srel = QE[row1 + (m - l - 2)];
                        out[e] = (acc[mi][ni][2 * h + e] + srel) * scale;
                    }
                    *reinterpret_cast<float2*>(C + (size_t)l * N + c0) =
                        make_float2(out[0], out[1]);
                }
            }
        }
    }
}

// ---------------------------------------------------------------------------
// Row softmax over 2048 elements: one block per row, 256 threads x 8 elements.
// ---------------------------------------------------------------------------
__global__ void softmax2048(float* __restrict__ S)
{
    __shared__ float red[8];
    const size_t row = blockIdx.x;
    float* p = S + row * (size_t)L_;
    const int tid = threadIdx.x;

    float v[8];
    float mx = -1e30f;
#pragma unroll
    for (int i = 0; i < 8; i++) {
        v[i] = p[tid + i * 256];
        mx = fmaxf(mx, v[i]);
    }
#pragma unroll
    for (int o = 16; o > 0; o >>= 1)
        mx = fmaxf(mx, __shfl_xor_sync(0xffffffffu, mx, o));
    if ((tid & 31) == 0) red[tid >> 5] = mx;
    __syncthreads();
    mx = red[0];
#pragma unroll
    for (int w = 1; w < 8; w++) mx = fmaxf(mx, red[w]);
    __syncthreads();

    float sum = 0.f;
#pragma unroll
    for (int i = 0; i < 8; i++) {
        v[i] = __expf(v[i] - mx);
        sum += v[i];
    }
#pragma unroll
    for (int o = 16; o > 0; o >>= 1)
        sum += __shfl_xor_sync(0xffffffffu, sum, o);
    if ((tid & 31) == 0) red[tid >> 5] = sum;
    __syncthreads();
    float tot = 0.f;
#pragma unroll
    for (int w = 0; w < 8; w++) tot += red[w];

    const float inv = 1.f / tot;
#pragma unroll
    for (int i = 0; i < 8; i++) p[tid + i * 256] = v[i] * inv;
}

// ---------------------------------------------------------------------------
extern "C" void kernel_launch(void* const* d_in, const int* in_sizes, int n_in,
                              void* d_out, int out_size)
{
    const float* inQ = (const float*)d_in[0];
    const float* inK = (const float*)d_in[1];
    const float* inV = (const float*)d_in[2];
    const float* Wq  = (const float*)d_in[3];
    const float* Wk  = (const float*)d_in[4];
    const float* Wv  = (const float*)d_in[5];
    const float* E   = (const float*)d_in[6];
    float* out = (float*)d_out;

    float *Q, *K, *Vt, *QE, *S;
    cudaGetSymbolAddress((void**)&Q,  g_Q);
    cudaGetSymbolAddress((void**)&K,  g_K);
    cudaGetSymbolAddress((void**)&Vt, g_Vt);
    cudaGetSymbolAddress((void**)&QE, g_QE);
    cudaGetSymbolAddress((void**)&S,  g_S);

    // Projections: [8192,512] x [512,{256,256,512}] (NN)
    tgemm<false, false, false><<<dim3(DK_ / 128, BL_ / 128, 1), 256>>>(
        inQ, Wq, Q, BL_, DK_, D_, DK_, 0, 0, 0, nullptr);
    tgemm<false, false, false><<<dim3(DK_ / 128, BL_ / 128, 1), 256>>>(
        inK, Wk, K, BL_, DK_, D_, DK_, 0, 0, 0, nullptr);
    // V projection with transposed store: Vt[512, 8192]
    tgemm<false, false, true><<<dim3(D_ / 128, BL_ / 128, 1), 256>>>(
        inV, Wv, Vt, BL_, D_, D_, D_, 0, 0, 0, nullptr);

    // QE = Q * E^T : [8192,256] x [2048,256]^T -> [8192,2048] (NT)
    tgemm<true, false, false><<<dim3(L_ / 128, BL_ / 128, 1), 256>>>(
        Q, E, QE, BL_, L_, DK_, DK_, 0, 0, 0, nullptr);

    // S = (Q K^T + skew(QE)) / 16, batched over B (NT + skew epilogue)
    tgemm<true, true, false><<<dim3(L_ / 128, L_ / 128, B_), 256>>>(
        Q, K, S, L_, L_, DK_, DK_,
        (long long)L_ * DK_, (long long)L_ * DK_, (long long)L_ * L_, QE);

    // softmax along rows
    softmax2048<<<BL_, 256>>>(S);

    // out = P * Vt^T, batched over B (NT): B = Vt rows [512], row stride BL_,
    // batch offset b*L_ along the row.
    tgemm<true, false, false><<<dim3(D_ / 128, L_ / 128, B_), 256>>>(
        S, Vt, out, L_, D_, L_, BL_,
        (long long)L_ * L_, (long long)L_, (long long)L_ * D_, nullptr);
}

// round 17
// speedup vs baseline: 1.4870x; 1.4870x over previous
#include <cuda_runtime.h>
#include <cstdint>

#define B_  4
#define L_  2048
#define D_  512
#define DK_ 256
#define BL_ (B_ * L_)

// Scratch (allocation-free per harness rules)
__device__ float g_Q[BL_ * DK_];
__device__ float g_K[BL_ * DK_];
__device__ float g_V[BL_ * D_];
__device__ float g_Vt[(size_t)D_ * BL_];        // V transposed: [512, 8192]
__device__ float g_QE[(size_t)BL_ * L_];
__device__ float g_S[(size_t)BL_ * L_];

__device__ __forceinline__ uint32_t cvt_tf32(float x) {
    uint32_t r;
    asm("cvt.rna.tf32.f32 %0, %1;" : "=r"(r) : "f"(x));
    return r;
}

__device__ __forceinline__ void mma_tf32(float c[4], const uint32_t a[4], const uint32_t b[2]) {
    asm volatile(
        "mma.sync.aligned.m16n8k8.row.col.f32.tf32.tf32.f32 "
        "{%0,%1,%2,%3},{%4,%5,%6,%7},{%8,%9},{%0,%1,%2,%3};"
        : "+f"(c[0]), "+f"(c[1]), "+f"(c[2]), "+f"(c[3])
        : "r"(a[0]), "r"(a[1]), "r"(a[2]), "r"(a[3]), "r"(b[0]), "r"(b[1]));
}

__device__ __forceinline__ void ldsm4(uint32_t& r0, uint32_t& r1, uint32_t& r2, uint32_t& r3,
                                      uint32_t addr) {
    asm volatile("ldmatrix.sync.aligned.m8n8.x4.shared.b16 {%0,%1,%2,%3}, [%4];"
                 : "=r"(r0), "=r"(r1), "=r"(r2), "=r"(r3) : "r"(addr));
}

// ---------------------------------------------------------------------------
// TF32 tensor-core GEMM (R10-winning structure: static smem, single-stage,
// register prefetch, ldmatrix fragments, 2 syncs/chunk). Block tile 128x128,
// K-chunk 32, 256 threads = 8 warps (2x4 grid, warp tile 64x32), fp32 accum.
//   TRANS_B=false: C = A[M,K] * B[K,N]   (B row-major, row stride ldB = N)
//   TRANS_B=true : C = A[M,K] * B[N,K]^T (B row stride ldB)
//   SKEW=true    : C = (A*B^T + skew(QE)) * 1/16 (QK^T epilogue)
// ---------------------------------------------------------------------------
template <bool TRANS_B, bool SKEW>
__global__ __launch_bounds__(256)
void tgemm(const float* __restrict__ A, const float* __restrict__ Bm,
           float* __restrict__ C, int M, int N, int Kd, int ldB,
           long long sA, long long sB, long long sC,
           const float* __restrict__ QE)
{
    __shared__ uint32_t As[128 * 36];
    __shared__ uint32_t Bs[TRANS_B ? (128 * 36) : (32 * 136)];

    const int bz = blockIdx.z;
    A  += (size_t)bz * sA;
    Bm += (size_t)bz * sB;
    C  += (size_t)bz * sC;

    const int bm = blockIdx.y * 128;
    const int bn = blockIdx.x * 128;
    const int tid  = threadIdx.x;
    const int lane = tid & 31;
    const int warp = tid >> 5;
    const int wm = warp & 1;   // 0..1  (64-row slab)
    const int wn = warp >> 1;  // 0..3  (32-col slab)

    const int arow  = tid >> 3;          // 0..31
    const int acol4 = (tid & 7) << 2;    // 0,4,..28
    const int brow  = tid >> 5;          // 0..7   (NN)
    const int bcol4 = (tid & 31) << 2;   // 0..124 (NN)

    // ldmatrix per-lane base addresses (bytes)
    const uint32_t asm0 = (uint32_t)__cvta_generic_to_shared(As);
    const uint32_t bsm0 = (uint32_t)__cvta_generic_to_shared(Bs);
    const int l7 = lane & 7;
    const int lA_m = (lane >> 3) & 1;
    const int lA_k = lane >> 4;
    uint32_t aaddr[4];
#pragma unroll
    for (int mi = 0; mi < 4; mi++)
        aaddr[mi] = asm0 + ((wm * 64 + mi * 16 + l7 + 8 * lA_m) * 36 + 4 * lA_k) * 4;
    uint32_t baddr[2];
    if (TRANS_B) {
        const int lB_n = lane >> 4;
        const int lB_k = (lane >> 3) & 1;
#pragma unroll
        for (int n2 = 0; n2 < 2; n2++)
            baddr[n2] = bsm0 + ((wn * 32 + n2 * 16 + l7 + 8 * lB_n) * 36 + 4 * lB_k) * 4;
    }

    float acc[4][4][4];
#pragma unroll
    for (int i = 0; i < 4; i++)
#pragma unroll
        for (int j = 0; j < 4; j++)
#pragma unroll
            for (int e = 0; e < 4; e++) acc[i][j][e] = 0.f;

    float4 ra[4], rb[4];

    // ---- prologue global load (k0 = 0) ----
#pragma unroll
    for (int i = 0; i < 4; i++)
        ra[i] = *reinterpret_cast<const float4*>(
            A + (size_t)(bm + arow + 32 * i) * Kd + acol4);
#pragma unroll
    for (int i = 0; i < 4; i++) {
        if (TRANS_B)
            rb[i] = *reinterpret_cast<const float4*>(
                Bm + (size_t)(bn + arow + 32 * i) * ldB + acol4);
        else
            rb[i] = *reinterpret_cast<const float4*>(
                Bm + (size_t)(brow + 8 * i) * ldB + bn + bcol4);
    }

    for (int k0 = 0; k0 < Kd; k0 += 32) {
        // ---- store tiles to smem (cvt to tf32 bits) ----
#pragma unroll
        for (int i = 0; i < 4; i++)
            *reinterpret_cast<uint4*>(&As[(arow + 32 * i) * 36 + acol4]) =
                make_uint4(cvt_tf32(ra[i].x), cvt_tf32(ra[i].y),
                           cvt_tf32(ra[i].z), cvt_tf32(ra[i].w));
#pragma unroll
        for (int i = 0; i < 4; i++) {
            if (TRANS_B)
                *reinterpret_cast<uint4*>(&Bs[(arow + 32 * i) * 36 + acol4]) =
                    make_uint4(cvt_tf32(rb[i].x), cvt_tf32(rb[i].y),
                               cvt_tf32(rb[i].z), cvt_tf32(rb[i].w));
            else
                *reinterpret_cast<uint4*>(&Bs[(brow + 8 * i) * 136 + bcol4]) =
                    make_uint4(cvt_tf32(rb[i].x), cvt_tf32(rb[i].y),
                               cvt_tf32(rb[i].z), cvt_tf32(rb[i].w));
        }
        __syncthreads();

        // ---- prefetch next chunk into registers ----
        if (k0 + 32 < Kd) {
            const int kn = k0 + 32;
#pragma unroll
            for (int i = 0; i < 4; i++)
                ra[i] = *reinterpret_cast<const float4*>(
                    A + (size_t)(bm + arow + 32 * i) * Kd + kn + acol4);
#pragma unroll
            for (int i = 0; i < 4; i++) {
                if (TRANS_B)
                    rb[i] = *reinterpret_cast<const float4*>(
                        Bm + (size_t)(bn + arow + 32 * i) * ldB + kn + acol4);
                else
                    rb[i] = *reinterpret_cast<const float4*>(
                        Bm + (size_t)(kn + brow + 8 * i) * ldB + bn + bcol4);
            }
        }

        // ---- compute: 4 k8-steps, fragments via ldmatrix ----
#pragma unroll
        for (int kb = 0; kb < 4; kb++) {
            const uint32_t koff = (uint32_t)(kb * 8 * 4);  // bytes
            uint32_t af[4][4];
#pragma unroll
            for (int mi = 0; mi < 4; mi++)
                ldsm4(af[mi][0], af[mi][1], af[mi][2], af[mi][3], aaddr[mi] + koff);
            uint32_t bf[4][2];
            if (TRANS_B) {
#pragma unroll
                for (int n2 = 0; n2 < 2; n2++)
                    ldsm4(bf[2 * n2][0], bf[2 * n2][1], bf[2 * n2 + 1][0], bf[2 * n2 + 1][1],
                          baddr[n2] + koff);
            } else {
                const int kk = kb * 8;
#pragma unroll
                for (int ni = 0; ni < 4; ni++) {
                    const int n = wn * 32 + ni * 8 + (lane >> 2);
                    bf[ni][0] = Bs[(kk + (lane & 3)) * 136 + n];
                    bf[ni][1] = Bs[(kk + 4 + (lane & 3)) * 136 + n];
                }
            }
#pragma unroll
            for (int mi = 0; mi < 4; mi++)
#pragma unroll
                for (int ni = 0; ni < 4; ni++)
                    mma_tf32(acc[mi][ni], af[mi], bf[ni]);
        }
        __syncthreads();
    }

    // ---- epilogue ----
    if (!SKEW) {
#pragma unroll
        for (int mi = 0; mi < 4; mi++) {
            const int r0 = bm + wm * 64 + mi * 16 + (lane >> 2);
#pragma unroll
            for (int ni = 0; ni < 4; ni++) {
                const int c0 = bn + wn * 32 + ni * 8 + 2 * (lane & 3);
                *reinterpret_cast<float2*>(C + (size_t)r0 * N + c0) =
                    make_float2(acc[mi][ni][0], acc[mi][ni][1]);
                *reinterpret_cast<float2*>(C + (size_t)(r0 + 8) * N + c0) =
                    make_float2(acc[mi][ni][2], acc[mi][ni][3]);
            }
        }
    } else {
        // Srel[l,m] = QE[l, m-l+L-1] (m<=l); 0 (m==l+1); QE[l+1, m-l-2] (m>=l+2)
        const float scale = 0.0625f;  // 1/sqrt(256)
        const int b = blockIdx.z;
#pragma unroll
        for (int mi = 0; mi < 4; mi++) {
            const int rbase = bm + wm * 64 + mi * 16 + (lane >> 2);
#pragma unroll
            for (int ni = 0; ni < 4; ni++) {
                const int c0 = bn + wn * 32 + ni * 8 + 2 * (lane & 3);
#pragma unroll
                for (int h = 0; h < 2; h++) {
                    const int l = rbase + 8 * h;
                    const size_t row0 = (size_t)(b * L_ + l) * L_;
                    const size_t row1 = (size_t)(b * L_ + l + 1) * L_;
                    float out[2];
#pragma unroll
                    for (int e = 0; e < 2; e++) {
                        const int m = c0 + e;
                        float srel;
                        if (m <= l)          srel = QE[row0 + (m - l + L_ - 1)];
                        else if (m == l + 1) srel = 0.f;
                        else                 srel = QE[row1 + (m - l - 2)];
                        out[e] = (acc[mi][ni][2 * h + e] + srel) * scale;
                    }
                    *reinterpret_cast<float2*>(C + (size_t)l * N + c0) =
                        make_float2(out[0], out[1]);
                }
            }
        }
    }
}

// ---------------------------------------------------------------------------
// Tile transpose: Vt[512, 8192] = V[8192, 512]^T. Coalesced both sides.
// ---------------------------------------------------------------------------
__global__ void transpose_v(const float* __restrict__ in, float* __restrict__ out)
{
    __shared__ float t[32][33];
    const int x0 = blockIdx.x * 32;  // column in V  (row in Vt)
    const int y0 = blockIdx.y * 32;  // row in V
    const int tx = threadIdx.x, ty = threadIdx.y;  // 32 x 8
#pragma unroll
    for (int i = 0; i < 4; i++)
        t[ty + 8 * i][tx] = in[(size_t)(y0 + ty + 8 * i) * D_ + x0 + tx];
    __syncthreads();
#pragma unroll
    for (int i = 0; i < 4; i++)
        out[(size_t)(x0 + ty + 8 * i) * BL_ + y0 + tx] = t[tx][ty + 8 * i];
}

// ---------------------------------------------------------------------------
// Row softmax over 2048 elements: one block per row, 256 threads x 8 elements.
// ---------------------------------------------------------------------------
__global__ void softmax2048(float* __restrict__ S)
{
    __shared__ float red[8];
    const size_t row = blockIdx.x;
    float* p = S + row * (size_t)L_;
    const int tid = threadIdx.x;

    float v[8];
    float mx = -1e30f;
#pragma unroll
    for (int i = 0; i < 8; i++) {
        v[i] = p[tid + i * 256];
        mx = fmaxf(mx, v[i]);
    }
#pragma unroll
    for (int o = 16; o > 0; o >>= 1)
        mx = fmaxf(mx, __shfl_xor_sync(0xffffffffu, mx, o));
    if ((tid & 31) == 0) red[tid >> 5] = mx;
    __syncthreads();
    mx = red[0];
#pragma unroll
    for (int w = 1; w < 8; w++) mx = fmaxf(mx, red[w]);
    __syncthreads();

    float sum = 0.f;
#pragma unroll
    for (int i = 0; i < 8; i++) {
        v[i] = __expf(v[i] - mx);
        sum += v[i];
    }
#pragma unroll
    for (int o = 16; o > 0; o >>= 1)
        sum += __shfl_xor_sync(0xffffffffu, sum, o);
    if ((tid & 31) == 0) red[tid >> 5] = sum;
    __syncthreads();
    float tot = 0.f;
#pragma unroll
    for (int w = 0; w < 8; w++) tot += red[w];

    const float inv = 1.f / tot;
#pragma unroll
    for (int i = 0; i < 8; i++) p[tid + i * 256] = v[i] * inv;
}

// ---------------------------------------------------------------------------
extern "C" void kernel_launch(void* const* d_in, const int* in_sizes, int n_in,
                              void* d_out, int out_size)
{
    const float* inQ = (const float*)d_in[0];
    const float* inK = (const float*)d_in[1];
    const float* inV = (const float*)d_in[2];
    const float* Wq  = (const float*)d_in[3];
    const float* Wk  = (const float*)d_in[4];
    const float* Wv  = (const float*)d_in[5];
    const float* E   = (const float*)d_in[6];
    float* out = (float*)d_out;

    float *Q, *K, *V, *Vt, *QE, *S;
    cudaGetSymbolAddress((void**)&Q,  g_Q);
    cudaGetSymbolAddress((void**)&K,  g_K);
    cudaGetSymbolAddress((void**)&V,  g_V);
    cudaGetSymbolAddress((void**)&Vt, g_Vt);
    cudaGetSymbolAddress((void**)&QE, g_QE);
    cudaGetSymbolAddress((void**)&S,  g_S);

    // Projections: [8192,512] x [512,{256,256,512}] (NN)
    tgemm<false, false><<<dim3(DK_ / 128, BL_ / 128, 1), 256>>>(
        inQ, Wq, Q, BL_, DK_, D_, DK_, 0, 0, 0, nullptr);
    tgemm<false, false><<<dim3(DK_ / 128, BL_ / 128, 1), 256>>>(
        inK, Wk, K, BL_, DK_, D_, DK_, 0, 0, 0, nullptr);
    tgemm<false, false><<<dim3(D_ / 128, BL_ / 128, 1), 256>>>(
        inV, Wv, V, BL_, D_, D_, D_, 0, 0, 0, nullptr);

    // Vt = V^T (coalesced tile transpose)
    transpose_v<<<dim3(D_ / 32, BL_ / 32), dim3(32, 8)>>>(V, Vt);

    // QE = Q * E^T : [8192,256] x [2048,256]^T -> [8192,2048] (NT)
    tgemm<true, false><<<dim3(L_ / 128, BL_ / 128, 1), 256>>>(
        Q, E, QE, BL_, L_, DK_, DK_, 0, 0, 0, nullptr);

    // S = (Q K^T + skew(QE)) / 16, batched over B (NT + skew epilogue)
    tgemm<true, true><<<dim3(L_ / 128, L_ / 128, B_), 256>>>(
        Q, K, S, L_, L_, DK_, DK_,
        (long long)L_ * DK_, (long long)L_ * DK_, (long long)L_ * L_, QE);

    // softmax along rows
    softmax2048<<<BL_, 256>>>(S);

    // out = P * Vt^T, batched over B (NT): B = Vt rows (512 of them),
    // row stride BL_, batch offset b*2048 along the row (sB = 2048).
    tgemm<true, false><<<dim3(D_ / 128, L_ / 128, B_), 256>>>(
        S, Vt, out, L_, D_, L_, BL_,
        (long long)L_ * L_, (long long)L_, (long long)L_ * D_, nullptr);
}